// round 9
// baseline (speedup 1.0000x reference)
#include <cuda_runtime.h>

// Problem constants
#define NB   512      // batches
#define NL   512      // stream length
#define NC   8        // channels
#define NSEG 8        // segments per batch (Chen-associative split)
#define SEGLEN 64     // increments per segment (last has 63)
#define SIGSZ 584     // 8 + 64 + 512
#define NINC (NL - 1) // 511
#define SBUF 592      // padded per-group smem buffer (>= 584 and >= SEGLEN*NC)

// ---------------------------------------------------------------------------
// Fused signature kernel: 1 block = 1 batch, 512 threads = 8 groups of 64.
// Group g scans segment g (thread w = i*8+j owns S1[i]/2, S2[i,j], S3[i,j,:]),
// then the 8 partial signatures are tree-folded in shared memory (3 rounds):
//   r1: 0<-0o1  2<-2o3  4<-4o5  6<-6o7
//   r2: 0<-0o2  4<-4o6
//   r3: 0<-0o4   -> write out
// Chen fold (old A on RHS): S3 += B3 + A1(x)B2 + A2(x)B1; S2 += B2 + A1(x)B1;
// S1 += B1.
//
// RACE FIX vs previous round: a group is TWO warps; the sig publish reuses the
// group's own increment buffer, so a __syncthreads() must separate the scan
// (reads sdx) from the publish (writes sdx).
// ---------------------------------------------------------------------------

struct SigRegs {
    float A1;     // A1[i]
    float A2;     // A2[i,j]
    float A3[8];  // A3[i,j,0..7]
};

__device__ __forceinline__ void sig_store_smem(float* __restrict__ sb,
                                               const SigRegs& S, int w, int i, int j) {
    if (j == 0) sb[i] = S.A1;
    sb[8 + w] = S.A2;
    *(float4*)(sb + 72 + w * 8)     = make_float4(S.A3[0], S.A3[1], S.A3[2], S.A3[3]);
    *(float4*)(sb + 72 + w * 8 + 4) = make_float4(S.A3[4], S.A3[5], S.A3[6], S.A3[7]);
}

__device__ __forceinline__ void sig_fold(SigRegs& S, const float* __restrict__ sb,
                                         int w, int i, int j) {
    const float B1i  = sb[i];
    const float B1j  = sb[j];
    const float B2ij = sb[8 + w];
    float4 x0 = *(const float4*)(sb);
    float4 x1 = *(const float4*)(sb + 4);
    float4 y0 = *(const float4*)(sb + 8 + j * 8);       // B2[j, 0..3]
    float4 y1 = *(const float4*)(sb + 8 + j * 8 + 4);   // B2[j, 4..7]
    float4 z0 = *(const float4*)(sb + 72 + w * 8);
    float4 z1 = *(const float4*)(sb + 72 + w * 8 + 4);

    float b1v[8] = {x0.x, x0.y, x0.z, x0.w, x1.x, x1.y, x1.z, x1.w};
    float b2v[8] = {y0.x, y0.y, y0.z, y0.w, y1.x, y1.y, y1.z, y1.w};
    float b3v[8] = {z0.x, z0.y, z0.z, z0.w, z1.x, z1.y, z1.z, z1.w};

    #pragma unroll
    for (int k = 0; k < 8; k++)  // uses OLD A1, A2
        S.A3[k] = fmaf(S.A1, b2v[k], fmaf(S.A2, b1v[k], S.A3[k] + b3v[k]));
    S.A2 = fmaf(S.A1, B1j, S.A2 + B2ij);
    S.A1 = S.A1 + B1i;
}

__global__ __launch_bounds__(512, 3) void sig_kernel(const float* __restrict__ path,
                                                     float* __restrict__ out) {
    // Per-group buffer: holds SEGLEN*NC=512 increment floats during the scan,
    // then reused as a 584-float signature buffer during the fold. 18.5 KB.
    __shared__ __align__(16) float sdx[NSEG][SBUF];

    const int tid = threadIdx.x;
    const int g   = tid >> 6;        // group = segment (0..7)
    const int w   = tid & 63;
    const int i   = w >> 3;
    const int j   = w & 7;
    const int batch = blockIdx.x;
    const int t0    = g * SEGLEN;
    const int nsteps = (g == NSEG - 1) ? (NINC - (NSEG - 1) * SEGLEN) : SEGLEN; // 63/64

    // ---- stage increments for this group's segment ----
    const float* __restrict__ pb = path + (size_t)batch * NL * NC + (size_t)t0 * NC;
    for (int e = w; e < nsteps * NC; e += 64)
        sdx[g][e] = pb[e + NC] - pb[e];
    __syncthreads();

    // ---- sequential scan over this segment ----
    // Per step (old S1h, S2 on RHS):
    //   m = dxi/6 + S1h ; coeff = dxj*m + S2 ; n = 3m - S1h (= dxi/2 + S1)
    //   S2 += dxj*n ; S3[k] += coeff*dx_k ; S1h += dxi/2
    float S1h = 0.f;
    float S2  = 0.f;
    float S3[8];
    #pragma unroll
    for (int k = 0; k < 8; k++) S3[k] = 0.f;

    const float* __restrict__ dxp = sdx[g];
    #pragma unroll 4
    for (int t = 0; t < nsteps; t++) {
        const float4 d0 = *(const float4*)(dxp + t * 8);
        const float4 d1 = *(const float4*)(dxp + t * 8 + 4);
        const float dxi = dxp[t * 8 + i];
        const float dxj = dxp[t * 8 + j];

        const float m     = fmaf(dxi, 0.16666666666666666f, S1h);
        const float coeff = fmaf(dxj, m, S2);
        const float n     = fmaf(3.0f, m, -S1h);
        S2 = fmaf(dxj, n, S2);

        S3[0] = fmaf(coeff, d0.x, S3[0]);
        S3[1] = fmaf(coeff, d0.y, S3[1]);
        S3[2] = fmaf(coeff, d0.z, S3[2]);
        S3[3] = fmaf(coeff, d0.w, S3[3]);
        S3[4] = fmaf(coeff, d1.x, S3[4]);
        S3[5] = fmaf(coeff, d1.y, S3[5]);
        S3[6] = fmaf(coeff, d1.z, S3[6]);
        S3[7] = fmaf(coeff, d1.w, S3[7]);

        S1h = fmaf(0.5f, dxi, S1h);
    }

    SigRegs S;
    S.A1 = 2.f * S1h;
    S.A2 = S2;
    #pragma unroll
    for (int k = 0; k < 8; k++) S.A3[k] = S3[k];

    // RACE FIX: all warps must finish READING increments from sdx before any
    // group overwrites its buffer with signature data.
    __syncthreads();

    // ---- in-block tree fold (reuse sdx buffers as sig buffers) ----
    if (g & 1) sig_store_smem(sdx[g], S, w, i, j);
    __syncthreads();

    // round 1: 0<-0o1, 2<-2o3, 4<-4o5, 6<-6o7 ; groups 2,6 publish results
    if ((g & 1) == 0) {
        sig_fold(S, sdx[g + 1], w, i, j);
        if (g == 2 || g == 6) sig_store_smem(sdx[g], S, w, i, j);
    }
    __syncthreads();

    // round 2: 0<-0o2, 4<-4o6 ; group 4 publishes result
    if (g == 0) sig_fold(S, sdx[2], w, i, j);
    if (g == 4) {
        sig_fold(S, sdx[6], w, i, j);
        sig_store_smem(sdx[4], S, w, i, j);
    }
    __syncthreads();

    // round 3: 0<-0o4 ; write result
    if (g == 0) {
        sig_fold(S, sdx[4], w, i, j);
        float* __restrict__ ob = out + (size_t)batch * SIGSZ;
        if (j == 0) ob[i] = S.A1;
        ob[8 + w] = S.A2;
        *(float4*)(ob + 72 + w * 8)     = make_float4(S.A3[0], S.A3[1], S.A3[2], S.A3[3]);
        *(float4*)(ob + 72 + w * 8 + 4) = make_float4(S.A3[4], S.A3[5], S.A3[6], S.A3[7]);
    }
}

extern "C" void kernel_launch(void* const* d_in, const int* in_sizes, int n_in,
                              void* d_out, int out_size) {
    const float* path = (const float*)d_in[0];
    float* out = (float*)d_out;
    sig_kernel<<<NB, 512>>>(path, out);   // one 512-thread block per batch
}

// round 10
// speedup vs baseline: 1.3636x; 1.3636x over previous
#include <cuda_runtime.h>

// Problem constants
#define NB   512      // batches
#define NL   512      // stream length
#define NC   8        // channels
#define NSEG 8        // segments per batch (Chen-associative split)
#define SEGLEN 64     // increments per segment (last has 63)
#define SIGSZ 584     // 8 + 64 + 512
#define NINC (NL - 1) // 511
#define SBUF 592      // padded per-group smem buffer (>= 584 and >= SEGLEN*NC)

// ---------------------------------------------------------------------------
// Fused signature kernel: 1 block = 1 batch, 256 threads = 8 warps.
// Warp g scans segment g. Thread t (lane) owns TWO pairs: (i,j0),(i,j0+1)
// with i = lane>>2, j0 = (lane&3)*2. State: S1h=S1[i]/2, S2[2], S3[2][8].
// Per step (old state on RHS), m/n shared between the 2 pairs:
//   m  = dxi/6 + S1h ; n = 3m - S1h (= dxi/2 + S1)
//   coeff_p = dxj_p*m + S2_p ; S2_p += dxj_p*n
//   S3[p][k] += coeff_p * dx_k ; S1h += dxi/2
// LDS per warp-step: d0,d1 (uniform .128) + dxi (.32) + dxj pair (.64) = 4 wf
// covering 2 pairs -> half the crossbar traffic of the 64-thread scheme.
// Then 8 partial signatures tree-fold in smem (3 rounds) and g0 writes out.
// ---------------------------------------------------------------------------

struct SigRegs {
    float A1;        // A1[i]
    float A2[2];     // A2[i,j0], A2[i,j0+1]
    float A3[2][8];  // A3[i,j0,:], A3[i,j0+1,:]
};

__device__ __forceinline__ void sig_store(float* __restrict__ sb,
                                          const SigRegs& S, int i, int j0) {
    if (j0 == 0) sb[i] = S.A1;
    *(float2*)(sb + 8 + i * 8 + j0) = make_float2(S.A2[0], S.A2[1]);
    float* b3 = sb + 72 + (i * 8 + j0) * 8;
    *(float4*)(b3)      = make_float4(S.A3[0][0], S.A3[0][1], S.A3[0][2], S.A3[0][3]);
    *(float4*)(b3 + 4)  = make_float4(S.A3[0][4], S.A3[0][5], S.A3[0][6], S.A3[0][7]);
    *(float4*)(b3 + 8)  = make_float4(S.A3[1][0], S.A3[1][1], S.A3[1][2], S.A3[1][3]);
    *(float4*)(b3 + 12) = make_float4(S.A3[1][4], S.A3[1][5], S.A3[1][6], S.A3[1][7]);
}

__device__ __forceinline__ void sig_fold(SigRegs& S, const float* __restrict__ sb,
                                         int i, int j0) {
    const float B1i = sb[i];
    const float2 B1j  = *(const float2*)(sb + j0);
    const float2 B2ij = *(const float2*)(sb + 8 + i * 8 + j0);
    float4 x0 = *(const float4*)(sb);
    float4 x1 = *(const float4*)(sb + 4);
    // B2 rows j0 and j0+1 are 16 contiguous floats
    float4 y0 = *(const float4*)(sb + 8 + j0 * 8);
    float4 y1 = *(const float4*)(sb + 8 + j0 * 8 + 4);
    float4 y2 = *(const float4*)(sb + 8 + j0 * 8 + 8);
    float4 y3 = *(const float4*)(sb + 8 + j0 * 8 + 12);
    const float* b3p = sb + 72 + (i * 8 + j0) * 8;
    float4 z0 = *(const float4*)(b3p);
    float4 z1 = *(const float4*)(b3p + 4);
    float4 z2 = *(const float4*)(b3p + 8);
    float4 z3 = *(const float4*)(b3p + 12);

    float b1v[8]    = {x0.x, x0.y, x0.z, x0.w, x1.x, x1.y, x1.z, x1.w};
    float b2v[2][8] = {{y0.x, y0.y, y0.z, y0.w, y1.x, y1.y, y1.z, y1.w},
                       {y2.x, y2.y, y2.z, y2.w, y3.x, y3.y, y3.z, y3.w}};
    float b3v[2][8] = {{z0.x, z0.y, z0.z, z0.w, z1.x, z1.y, z1.z, z1.w},
                       {z2.x, z2.y, z2.z, z2.w, z3.x, z3.y, z3.z, z3.w}};

    #pragma unroll
    for (int p = 0; p < 2; p++) {
        #pragma unroll
        for (int k = 0; k < 8; k++)  // uses OLD A1, A2
            S.A3[p][k] = fmaf(S.A1, b2v[p][k],
                         fmaf(S.A2[p], b1v[k], S.A3[p][k] + b3v[p][k]));
    }
    S.A2[0] = fmaf(S.A1, B1j.x, S.A2[0] + B2ij.x);   // old A1
    S.A2[1] = fmaf(S.A1, B1j.y, S.A2[1] + B2ij.y);
    S.A1 = S.A1 + B1i;
}

__global__ __launch_bounds__(256) void sig_kernel(const float* __restrict__ path,
                                                  float* __restrict__ out) {
    // Per-warp buffer: SEGLEN*NC=512 increment floats during the scan,
    // reused as a 584-float signature buffer for the fold. 18.5 KB total.
    __shared__ __align__(16) float sdx[NSEG][SBUF];

    const int tid  = threadIdx.x;
    const int g    = tid >> 5;        // warp = segment (0..7)
    const int lane = tid & 31;
    const int i    = lane >> 2;
    const int j0   = (lane & 3) << 1;
    const int batch = blockIdx.x;
    const int t0    = g * SEGLEN;
    const int nsteps = (g == NSEG - 1) ? (NINC - (NSEG - 1) * SEGLEN) : SEGLEN; // 63/64

    // ---- stage increments (float4) for this warp's segment ----
    {
        const float4* __restrict__ pb4 =
            (const float4*)(path + (size_t)batch * NL * NC + (size_t)t0 * NC);
        float4* __restrict__ s4 = (float4*)sdx[g];
        const int n4 = nsteps * 2;
        for (int v = lane; v < n4; v += 32) {
            float4 a = pb4[v];
            float4 b = pb4[v + 2];   // +8 floats = next step, same chans
            s4[v] = make_float4(b.x - a.x, b.y - a.y, b.z - a.z, b.w - a.w);
        }
    }
    __syncwarp();

    // ---- sequential scan over this segment (warp-private) ----
    float S1h = 0.f;
    float S20 = 0.f, S21 = 0.f;
    float S3[2][8];
    #pragma unroll
    for (int p = 0; p < 2; p++)
        #pragma unroll
        for (int k = 0; k < 8; k++) S3[p][k] = 0.f;

    const float* __restrict__ dxp = sdx[g];
    #pragma unroll 4
    for (int s = 0; s < nsteps; s++) {
        const float4 d0 = *(const float4*)(dxp + s * 8);
        const float4 d1 = *(const float4*)(dxp + s * 8 + 4);
        const float  dxi = dxp[s * 8 + i];
        const float2 dxj = *(const float2*)(dxp + s * 8 + j0);

        const float m = fmaf(dxi, 0.16666666666666666f, S1h);
        const float n = fmaf(3.0f, m, -S1h);          // dxi/2 + S1
        const float c0 = fmaf(dxj.x, m, S20);
        const float c1 = fmaf(dxj.y, m, S21);
        S20 = fmaf(dxj.x, n, S20);
        S21 = fmaf(dxj.y, n, S21);

        S3[0][0] = fmaf(c0, d0.x, S3[0][0]);
        S3[0][1] = fmaf(c0, d0.y, S3[0][1]);
        S3[0][2] = fmaf(c0, d0.z, S3[0][2]);
        S3[0][3] = fmaf(c0, d0.w, S3[0][3]);
        S3[0][4] = fmaf(c0, d1.x, S3[0][4]);
        S3[0][5] = fmaf(c0, d1.y, S3[0][5]);
        S3[0][6] = fmaf(c0, d1.z, S3[0][6]);
        S3[0][7] = fmaf(c0, d1.w, S3[0][7]);
        S3[1][0] = fmaf(c1, d0.x, S3[1][0]);
        S3[1][1] = fmaf(c1, d0.y, S3[1][1]);
        S3[1][2] = fmaf(c1, d0.z, S3[1][2]);
        S3[1][3] = fmaf(c1, d0.w, S3[1][3]);
        S3[1][4] = fmaf(c1, d1.x, S3[1][4]);
        S3[1][5] = fmaf(c1, d1.y, S3[1][5]);
        S3[1][6] = fmaf(c1, d1.z, S3[1][6]);
        S3[1][7] = fmaf(c1, d1.w, S3[1][7]);

        S1h = fmaf(0.5f, dxi, S1h);
    }

    SigRegs S;
    S.A1 = 2.f * S1h;
    S.A2[0] = S20; S.A2[1] = S21;
    #pragma unroll
    for (int p = 0; p < 2; p++)
        #pragma unroll
        for (int k = 0; k < 8; k++) S.A3[p][k] = S3[p][k];

    // scan reads -> publish writes to the SAME warp-private buffer:
    // warp-level fence is sufficient (single warp owns sdx[g]).
    __syncwarp();

    // ---- in-block tree fold ----
    if (g & 1) sig_store(sdx[g], S, i, j0);
    __syncthreads();

    // round 1: 0<-0o1, 2<-2o3, 4<-4o5, 6<-6o7 ; warps 2,6 publish results
    if ((g & 1) == 0) {
        sig_fold(S, sdx[g + 1], i, j0);
        if (g == 2 || g == 6) sig_store(sdx[g], S, i, j0);
    }
    __syncthreads();

    // round 2: 0<-0o2, 4<-4o6 ; warp 4 publishes result
    if (g == 0) sig_fold(S, sdx[2], i, j0);
    if (g == 4) {
        sig_fold(S, sdx[6], i, j0);
        sig_store(sdx[4], S, i, j0);
    }
    __syncthreads();

    // round 3: 0<-0o4 ; write result
    if (g == 0) {
        sig_fold(S, sdx[4], i, j0);
        float* __restrict__ ob = out + (size_t)batch * SIGSZ;
        if (j0 == 0) ob[i] = S.A1;
        *(float2*)(ob + 8 + i * 8 + j0) = make_float2(S.A2[0], S.A2[1]);
        float* b3 = ob + 72 + (i * 8 + j0) * 8;
        *(float4*)(b3)      = make_float4(S.A3[0][0], S.A3[0][1], S.A3[0][2], S.A3[0][3]);
        *(float4*)(b3 + 4)  = make_float4(S.A3[0][4], S.A3[0][5], S.A3[0][6], S.A3[0][7]);
        *(float4*)(b3 + 8)  = make_float4(S.A3[1][0], S.A3[1][1], S.A3[1][2], S.A3[1][3]);
        *(float4*)(b3 + 12) = make_float4(S.A3[1][4], S.A3[1][5], S.A3[1][6], S.A3[1][7]);
    }
}

extern "C" void kernel_launch(void* const* d_in, const int* in_sizes, int n_in,
                              void* d_out, int out_size) {
    const float* path = (const float*)d_in[0];
    float* out = (float*)d_out;
    sig_kernel<<<NB, 256>>>(path, out);   // one 256-thread block per batch
}